// round 5
// baseline (speedup 1.0000x reference)
#include <cuda_runtime.h>
#include <cstdint>

#define NT      512   // threads per CTA (16 warps)
#define CLUSTER 4     // CTAs per cluster; freqs split 128/CTA

__device__ __forceinline__ float frcp(float x) {
    float r; asm("rcp.approx.f32 %0, %1;" : "=f"(r) : "f"(x)); return r;
}
__device__ __forceinline__ float flg2(float x) {
    float r; asm("lg2.approx.f32 %0, %1;" : "=f"(r) : "f"(x)); return r;
}
__device__ __forceinline__ uint32_t smem_u32(const void* p) {
    uint32_t a;
    asm("{ .reg .u64 t; cvta.to.shared.u64 t, %1; cvt.u32.u64 %0, t; }" : "=r"(a) : "l"(p));
    return a;
}
__device__ __forceinline__ uint32_t my_rank() {
    uint32_t r; asm("mov.u32 %0, %%cluster_ctarank;" : "=r"(r)); return r;
}
__device__ __forceinline__ void st_cluster_f32(uint32_t local_addr, uint32_t rank, float v) {
    uint32_t remote;
    asm volatile("mapa.shared::cluster.u32 %0, %1, %2;" : "=r"(remote) : "r"(local_addr), "r"(rank));
    asm volatile("st.shared::cluster.f32 [%0], %1;" :: "r"(remote), "f"(v) : "memory");
}
// release-arrive on CTA `rank`'s mbarrier: orders THIS thread's prior cluster stores
__device__ __forceinline__ void mbar_arrive_remote(uint32_t local_mbar, uint32_t rank) {
    uint32_t remote;
    asm volatile("mapa.shared::cluster.u32 %0, %1, %2;" : "=r"(remote) : "r"(local_mbar), "r"(rank));
    asm volatile("mbarrier.arrive.release.cluster.shared::cluster.b64 _, [%0];"
                 :: "r"(remote) : "memory");
}
__device__ __forceinline__ void mbar_wait_acq_cluster(uint32_t mbar, uint32_t parity) {
    asm volatile(
        "{\n\t"
        ".reg .pred P;\n\t"
        "WAIT_%=:\n\t"
        "mbarrier.try_wait.parity.acquire.cluster.shared::cta.b64 P, [%0], %1;\n\t"
        "@!P bra WAIT_%=;\n\t"
        "}" :: "r"(mbar), "r"(parity) : "memory");
}
__device__ __forceinline__ void cluster_sync() {
    asm volatile("barrier.cluster.arrive.aligned;" ::: "memory");
    asm volatile("barrier.cluster.wait.aligned;" ::: "memory");
}

__global__ void __launch_bounds__(NT, 1) __cluster_dims__(CLUSTER, 1, 1)
sgd_filter_design_kernel(const float* __restrict__ sos_init,
                         const float* __restrict__ target_dB,
                         float* __restrict__ out)
{
    __shared__ float  sos[16][8];            // replicated filter state
    __shared__ float4 trig[128];             // this CTA's 128 freqs
    __shared__ float  ccs[128];              // per-freq weight (local freqs)
    __shared__ float  part[2][CLUSTER][96];  // double-buffered grad partials
    __shared__ __align__(16) unsigned long long mbar[2]; // double-buffered mbarriers

    const int tid  = threadIdx.x;
    const int warp = tid >> 5;
    const int lane = tid & 31;
    const int q    = tid >> 2;          // local freq 0..127
    const int g    = tid & 3;           // section group (4 sections each)
    const uint32_t rank = my_rank();
    const uint32_t mbar0 = smem_u32(&mbar[0]);

    if (tid == 0) {
        // 64 arrivals per phase: 16 warps x 4 source CTAs
        asm volatile("mbarrier.init.shared.b64 [%0], 64;" :: "r"(mbar0) : "memory");
        asm volatile("mbarrier.init.shared.b64 [%0], 64;" :: "r"(mbar0 + 8) : "memory");
    }
    if (tid < 96) sos[tid / 6][tid % 6] = sos_init[tid];

    // Per-thread trig for freq q (global index rank*128+q), double precision once.
    float tc1, ts1, tc2, ts2, tgt;
    {
        int gf = (int)rank * 128 + q;
        double w = (double)gf * (3.14159265358979323846 / 511.0);
        tc1 = (float)cos(w);        ts1 = (float)sin(w);
        tc2 = (float)cos(2.0 * w);  ts2 = (float)sin(2.0 * w);
        if (g == 0) trig[q] = make_float4(tc1, ts1, tc2, ts2);
        tgt = target_dB[gf];
    }
    __syncthreads();
    cluster_sync();   // barriers initialized everywhere before any DSMEM traffic

    const float KC   = 40.0f / (512.0f * 2.30258509299404568402f); // 2/n * 20/ln10
    const float DB2  = 6.02059991327962390427f;                    // 20*log10(2)
    const float EPS  = 1e-8f;
    const float LR   = 0.1f;

    for (int it = 0; it < 1000; ++it) {
        const int      buf    = it & 1;
        const uint32_t mb     = mbar0 + (uint32_t)(buf * 8);
        const uint32_t parity = (uint32_t)((it >> 1) & 1);

        // ---- Pass 1 (local): full |H| product; sections split across 4 lanes ----
        float pP = 1.0f;
#pragma unroll
        for (int j = 0; j < 4; ++j) {
            int s = g * 4 + j;
            float b0 = sos[s][0], b1 = sos[s][1], b2 = sos[s][2];
            float a0 = sos[s][3], a1 = sos[s][4], a2 = sos[s][5];
            float Br = fmaf(b2, tc2, fmaf(b1, tc1, b0));
            float Bi = -fmaf(b2, ts2, b1 * ts1);
            float Ar = fmaf(a2, tc2, fmaf(a1, tc1, a0));
            float Ai = -fmaf(a2, ts2, a1 * ts1);
            pP *= fmaf(Br, Br, Bi * Bi) * frcp(fmaf(Ar, Ar, Ai * Ai));
        }
        pP *= __shfl_xor_sync(0xffffffffu, pP, 1);
        pP *= __shfl_xor_sync(0xffffffffu, pP, 2);
        {
            float mag = sqrtf(pP);
            float mpe = mag + EPS;
            float dB  = DB2 * flg2(mpe);
            float cc  = KC * (dB - tgt) * (mag * frcp(mpe));
            if (g == 0) ccs[q] = cc;
        }
        __syncthreads();

        // ---- Pass 2: warp s integrates section s over this CTA's 128 freqs ----
        {
            const int s = warp;
            float b0 = sos[s][0], b1 = sos[s][1], b2 = sos[s][2];
            float a0 = sos[s][3], a1 = sos[s][4], a2 = sos[s][5];
            float g0 = 0.f, g1 = 0.f, g2 = 0.f, g3 = 0.f, g4 = 0.f, g5 = 0.f;
#pragma unroll
            for (int k = 0; k < 4; ++k) {
                int f = k * 32 + lane;
                float4 t = trig[f];
                float  c = ccs[f];
                float Br = fmaf(b2, t.z, fmaf(b1, t.x, b0));
                float Bi = -fmaf(b2, t.w, b1 * t.y);
                float Ar = fmaf(a2, t.z, fmaf(a1, t.x, a0));
                float Ai = -fmaf(a2, t.w, a1 * t.y);
                float cB =  c * frcp(fmaf(Br, Br, Bi * Bi));
                float cA = -c * frcp(fmaf(Ar, Ar, Ai * Ai));
                g0 = fmaf(cB, Br, g0);
                g1 = fmaf(cB, fmaf(t.x, Br, -t.y * Bi), g1);
                g2 = fmaf(cB, fmaf(t.z, Br, -t.w * Bi), g2);
                g3 = fmaf(cA, Ar, g3);
                g4 = fmaf(cA, fmaf(t.x, Ar, -t.y * Ai), g4);
                g5 = fmaf(cA, fmaf(t.z, Ar, -t.w * Ai), g5);
            }
#pragma unroll
            for (int o = 16; o > 0; o >>= 1) {
                g0 += __shfl_xor_sync(0xffffffffu, g0, o);
                g1 += __shfl_xor_sync(0xffffffffu, g1, o);
                g2 += __shfl_xor_sync(0xffffffffu, g2, o);
                g3 += __shfl_xor_sync(0xffffffffu, g3, o);
                g4 += __shfl_xor_sync(0xffffffffu, g4, o);
                g5 += __shfl_xor_sync(0xffffffffu, g5, o);
            }
            // lane L ships this CTA's partial for section s to CTA L, then
            // release-arrives on CTA L's current barrier (orders own stores).
            if (lane < CLUSTER) {
                uint32_t base = smem_u32(&part[buf][rank][s * 6]);
                st_cluster_f32(base +  0, (uint32_t)lane, g0);
                st_cluster_f32(base +  4, (uint32_t)lane, g1);
                st_cluster_f32(base +  8, (uint32_t)lane, g2);
                st_cluster_f32(base + 12, (uint32_t)lane, g3);
                st_cluster_f32(base + 16, (uint32_t)lane, g4);
                st_cluster_f32(base + 20, (uint32_t)lane, g5);
                mbar_arrive_remote(mb, (uint32_t)lane);
            }
        }

        // ---- wait for all 64 arrivals (acquire: remote partials visible) ----
        mbar_wait_acq_cluster(mb, parity);

        // ---- SGD update (replicated, fixed summation order) ----
        if (tid < 96) {
            const float* p0 = part[buf][0];
            const float* p1 = part[buf][1];
            const float* p2 = part[buf][2];
            const float* p3 = part[buf][3];
            float gr = (p0[tid] + p1[tid]) + (p2[tid] + p3[tid]);
            sos[tid / 6][tid % 6] -= LR * gr;
        }
        __syncthreads();
    }

    if (rank == 0 && tid < 96) out[tid] = sos[tid / 6][tid % 6];
    cluster_sync();   // no CTA exits while peers may still target its smem
}

extern "C" void kernel_launch(void* const* d_in, const int* in_sizes, int n_in,
                              void* d_out, int out_size) {
    const float* sos_init  = (const float*)d_in[0];   // [16,6] = 96 floats
    const float* target_dB = (const float*)d_in[1];   // [512]
    float* out = (float*)d_out;                       // [16,6] = 96 floats
    sgd_filter_design_kernel<<<CLUSTER, NT>>>(sos_init, target_dB, out);
}